// round 11
// baseline (speedup 1.0000x reference)
#include <cuda_runtime.h>
#include <cuda_fp16.h>
#include <cstdint>
#include <cstddef>

#define E_DIM 16
#define B_DIM 128
#define C_DIM 512
#define H_DIM 1024
#define D_DIM 130
#define DPAD  132            // fp32 Y row pad (528B, 16B-aligned)
#define DPH   136            // half prev row pad (16B-aligned rows)
#define S_DIM 16
#define NROW  2048
#define G3    3072
#define TROW  32768
#define OUT_T 256

// ---------------- scratch (static device globals) ----------------------------
__device__ __align__(16) __half g_H1h[NROW * H_DIM];
__device__ __align__(16) __half g_H2h[NROW * H_DIM];
__device__ __align__(16) __half g_HAh[(size_t)S_DIM * NROW * H_DIM];
__device__ __align__(16) __half g_PVh[(size_t)S_DIM * NROW * DPH];
__device__ __align__(16) __half g_CRh[NROW * C_DIM];
__device__ __align__(16) __half g_FIWh[2 * H_DIM * C_DIM];
__device__ __align__(16) __half g_W1Ch[G3 * C_DIM];
__device__ __align__(16) __half g_W1Ph[G3 * DPH];
__device__ __align__(16) __half g_W1Hh[G3 * H_DIM];
__device__ __align__(16) __half g_W2Ih[G3 * H_DIM];
__device__ __align__(16) __half g_W2Hh[G3 * H_DIM];
__device__ __align__(16) __half g_FOh[D_DIM * H_DIM];
// half GEMM outputs
__device__ __align__(16) __half g_TAh[NROW * G3];
__device__ __align__(16) __half g_TBh[NROW * G3];
__device__ __align__(16) __half g_PPsh[NROW * G3];        // prev-part, this step
__device__ __align__(16) __half g_CPh[NROW * G3];
__device__ __align__(16) __half g_T0h[NROW * 2 * H_DIM];
// fp32 final projection buffer
__device__ __align__(16) float g_Y[(size_t)TROW * DPAD];

// ---------------- helpers ----------------------------------------------------
__device__ __forceinline__ uint32_t smem_u32(const void* p) {
    uint32_t a;
    asm("{ .reg .u64 t; cvta.to.shared.u64 t, %1; cvt.u32.u64 %0, t; }"
        : "=r"(a) : "l"(p));
    return a;
}
__device__ __forceinline__ void mma_f16(float d[4], const uint32_t a[4],
                                        const uint32_t b[2]) {
    asm volatile(
        "mma.sync.aligned.m16n8k16.row.col.f32.f16.f16.f32 "
        "{%0,%1,%2,%3}, {%4,%5,%6,%7}, {%8,%9}, {%0,%1,%2,%3};\n"
        : "+f"(d[0]), "+f"(d[1]), "+f"(d[2]), "+f"(d[3])
        : "r"(a[0]), "r"(a[1]), "r"(a[2]), "r"(a[3]), "r"(b[0]), "r"(b[1]));
}

// ---------------- z-batched TN GEMM (half in; OUT=0 half, OUT=1 fp32) --------
struct GP {
    const __half *A, *B;
    const float* bias;
    void* C;                 // OUT 0: __half*, OUT 1: float*
    int lda, ldb, ldc, K, N;
};

#define RS   40                      // smem row stride in halves (80 B)
#define STG_B 20480                  // bytes per stage (A 10240 + B 10240)
#define ERW  68                      // epilogue fp32 row stride (64 + 4 pad)
#define GSMEM_BYTES (3 * STG_B)      // 61440; epilogue 128*68*4=34816 fits

// C[M,N] = A[M,K] * B[N,K]^T (+bias). M mult of 128. Tile 128x128x32(half),
// 4 warps (64x64), 3-stage cp.async (3 CTAs/SM), 2-pass transpose epilogue.
template <int OUT>
__global__ void __launch_bounds__(128, 3) gemm4(GP p0, GP p1, GP p2)
{
    extern __shared__ __half smh[];
    float* smf = (float*)smh;
    const GP p = (blockIdx.z == 0) ? p0 : ((blockIdx.z == 1) ? p1 : p2);
    const uint32_t smb = smem_u32(smh);
    const int tid  = threadIdx.x, lane = tid & 31, warp = tid >> 5;
    const int g    = lane >> 2, tg = lane & 3;
    const int wm   = (warp & 1) * 64, wn = (warp >> 1) * 64;
    const int bm0  = blockIdx.y * 128, bn0 = blockIdx.x * 128;
    const int KT   = (p.K + 31) / 32;
    const int lrow = tid >> 2, ci = tid & 3;

    float acc[4][8][4];
#pragma unroll
    for (int mi = 0; mi < 4; mi++)
#pragma unroll
        for (int ni = 0; ni < 8; ni++)
#pragma unroll
            for (int f = 0; f < 4; f++) acc[mi][ni][f] = 0.f;

#define LOADS(kt, st) do {                                                    \
    uint32_t ab = smb + (uint32_t)(st) * STG_B;                               \
    uint32_t bb = ab + STG_B / 2;                                             \
    int kc = (kt) * 32 + ci * 8;                                              \
    int sza = (kc < p.K) ? 16 : 0;                                            \
    _Pragma("unroll") for (int t = 0; t < 4; t++) {                           \
        int row = t * 32 + lrow;                                              \
        const __half* sa = sza ? (p.A + (size_t)(bm0 + row) * p.lda + kc)     \
                               : p.A;                                         \
        uint32_t da = ab + (uint32_t)(row * 80 + ci * 16);                    \
        asm volatile("cp.async.cg.shared.global [%0], [%1], 16, %2;"          \
                     :: "r"(da), "l"(sa), "r"(sza));                          \
        int gr = bn0 + row;                                                   \
        int szb = (sza && gr < p.N) ? 16 : 0;                                 \
        const __half* sb = szb ? (p.B + (size_t)gr * p.ldb + kc) : p.B;       \
        uint32_t db = bb + (uint32_t)(row * 80 + ci * 16);                    \
        asm volatile("cp.async.cg.shared.global [%0], [%1], 16, %2;"          \
                     :: "r"(db), "l"(sb), "r"(szb));                          \
    }                                                                         \
} while (0)

#define COMP(st) do {                                                         \
    const __half* As = smh + (size_t)(st) * (STG_B / 2);                      \
    const __half* Bs = As + STG_B / 4;                                        \
    _Pragma("unroll") for (int ks = 0; ks < 2; ks++) {                        \
        const int k0 = ks * 16 + tg * 2;                                      \
        uint32_t af[4][4], bf[8][2];                                          \
        _Pragma("unroll") for (int mi = 0; mi < 4; mi++) {                    \
            int r = wm + mi * 16 + g;                                         \
            af[mi][0] = *(const uint32_t*)&As[r * RS + k0];                   \
            af[mi][1] = *(const uint32_t*)&As[(r + 8) * RS + k0];             \
            af[mi][2] = *(const uint32_t*)&As[r * RS + k0 + 8];               \
            af[mi][3] = *(const uint32_t*)&As[(r + 8) * RS + k0 + 8];         \
        }                                                                     \
        _Pragma("unroll") for (int ni = 0; ni < 8; ni++) {                    \
            int n = wn + ni * 8 + g;                                          \
            bf[ni][0] = *(const uint32_t*)&Bs[n * RS + k0];                   \
            bf[ni][1] = *(const uint32_t*)&Bs[n * RS + k0 + 8];               \
        }                                                                     \
        _Pragma("unroll") for (int mi = 0; mi < 4; mi++)                      \
            _Pragma("unroll") for (int ni = 0; ni < 8; ni++)                  \
                mma_f16(acc[mi][ni], af[mi], bf[ni]);                         \
    }                                                                         \
} while (0)

    // 3-stage prologue
#pragma unroll
    for (int s = 0; s < 2; s++) {
        if (s < KT) LOADS(s, s);
        asm volatile("cp.async.commit_group;" ::: "memory");
    }
    for (int kt = 0; kt < KT; kt++) {
        asm volatile("cp.async.wait_group 1;" ::: "memory");
        __syncthreads();
        COMP(kt % 3);
        int nk = kt + 2;
        if (nk < KT) LOADS(nk, nk % 3);
        asm volatile("cp.async.commit_group;" ::: "memory");
    }
    asm volatile("cp.async.wait_group 0;" ::: "memory");
#undef LOADS
#undef COMP

    // ---- epilogue: two 64-column passes through smem transpose (+bias) -----
    const int colq = tid & 15;       // 16 groups of 4 columns
    const int rowb = tid >> 4;       // 8 row bases
#pragma unroll
    for (int nh = 0; nh < 2; nh++) {
        __syncthreads();             // prior pass reads / mainloop done
        if ((warp >> 1) == nh) {
#pragma unroll
            for (int mi = 0; mi < 4; mi++)
#pragma unroll
                for (int ni = 0; ni < 8; ni++) {
                    int r = wm + mi * 16 + g, cc = ni * 8 + 2 * tg;
                    *(float2*)&smf[r * ERW + cc] =
                        make_float2(acc[mi][ni][0], acc[mi][ni][1]);
                    *(float2*)&smf[(r + 8) * ERW + cc] =
                        make_float2(acc[mi][ni][2], acc[mi][ni][3]);
                }
        }
        __syncthreads();
        const int gn = bn0 + nh * 64 + colq * 4;
        float4 bv = make_float4(0.f, 0.f, 0.f, 0.f);
        if (p.bias) {
            if (gn < p.N)     bv.x = p.bias[gn];
            if (gn + 1 < p.N) bv.y = p.bias[gn + 1];
            if (gn + 2 < p.N) bv.z = p.bias[gn + 2];
            if (gn + 3 < p.N) bv.w = p.bias[gn + 3];
        }
#pragma unroll
        for (int j = 0; j < 16; j++) {
            int r = j * 8 + rowb;
            float4 v = *(float4*)&smf[r * ERW + colq * 4];
            v.x += bv.x; v.y += bv.y; v.z += bv.z; v.w += bv.w;
            if (OUT == 0) {
                __half* cp = (__half*)p.C + (size_t)(bm0 + r) * p.ldc + gn;
                if (gn + 3 < p.N) {
                    __half2 o0 = __floats2half2_rn(v.x, v.y);
                    __half2 o1 = __floats2half2_rn(v.z, v.w);
                    *(uint2*)cp = make_uint2(*(uint32_t*)&o0, *(uint32_t*)&o1);
                } else {
                    if (gn < p.N)     cp[0] = __float2half(v.x);
                    if (gn + 1 < p.N) cp[1] = __float2half(v.y);
                    if (gn + 2 < p.N) cp[2] = __float2half(v.z);
                    if (gn + 3 < p.N) cp[3] = __float2half(v.w);
                }
            } else {
                float* cp = (float*)p.C + (size_t)(bm0 + r) * p.ldc + gn;
                if (gn + 3 < p.N) {
                    *(float4*)cp = v;
                } else {
                    if (gn < p.N)     cp[0] = v.x;
                    if (gn + 1 < p.N) cp[1] = v.y;
                    if (gn + 2 < p.N) cp[2] = v.z;
                }
            }
        }
    }
}

// ---------------- elementwise kernels ----------------------------------------
__device__ __forceinline__ float sigf(float x) {
    return 1.f / (1.f + __expf(-x));
}
__device__ __forceinline__ float4 h4(const __half2* p, int i) {
    __half2 a = p[i], b = p[i + 1];
    return make_float4(__low2float(a), __high2float(a),
                       __low2float(b), __high2float(b));
}

// gi = gi1 (+gi2) (half); gh half; h half. 4 units/thread.
template <bool HAS_GI2, bool HAS_COPY>
__global__ void gate_kernel(const __half2* __restrict__ gi1,
                            const __half2* __restrict__ gi2,
                            const __half2* __restrict__ gh,
                            __half2* __restrict__ h,
                            __half2* __restrict__ hcopy)
{
    int v = blockIdx.x * blockDim.x + threadIdx.x;   // NROW*H/4
    int m = v >> 8, q = v & 255;
    int base = m * 1536 + 2 * q;                     // half2 units, G3/2=1536
    float4 ir = h4(gi1, base), iz = h4(gi1, base + 512),
           in = h4(gi1, base + 1024);
    if (HAS_GI2) {
        float4 a = h4(gi2, base), b = h4(gi2, base + 512),
               c = h4(gi2, base + 1024);
        ir.x += a.x; ir.y += a.y; ir.z += a.z; ir.w += a.w;
        iz.x += b.x; iz.y += b.y; iz.z += b.z; iz.w += b.w;
        in.x += c.x; in.y += c.y; in.z += c.z; in.w += c.w;
    }
    float4 hr = h4(gh, base), hz = h4(gh, base + 512),
           hn = h4(gh, base + 1024);
    float4 hv = h4(h, 2 * v);
    float4 o;
#define GATE1(cmp)                                                            \
    { float r = sigf(ir.cmp + hr.cmp), z = sigf(iz.cmp + hz.cmp);             \
      float n = tanhf(in.cmp + r * hn.cmp);                                   \
      o.cmp = (1.f - z) * n + z * hv.cmp; }
    GATE1(x) GATE1(y) GATE1(z) GATE1(w)
#undef GATE1
    __half2 o0 = __floats2half2_rn(o.x, o.y);
    __half2 o1 = __floats2half2_rn(o.z, o.w);
    h[2 * v] = o0;
    h[2 * v + 1] = o1;
    if (HAS_COPY) {
        hcopy[2 * v] = o0;
        hcopy[2 * v + 1] = o1;
    }
}

__global__ void init_tanh(const __half2* __restrict__ t0,
                          __half2* __restrict__ h1, __half2* __restrict__ h2)
{
    int v = blockIdx.x * blockDim.x + threadIdx.x;
    int m = v >> 8, q = v & 255;
    float4 a = h4(t0, m * 1024 + 2 * q);
    float4 b = h4(t0, m * 1024 + 512 + 2 * q);
    h1[2 * v]     = __floats2half2_rn(tanhf(a.x), tanhf(a.y));
    h1[2 * v + 1] = __floats2half2_rn(tanhf(a.z), tanhf(a.w));
    h2[2 * v]     = __floats2half2_rn(tanhf(b.x), tanhf(b.y));
    h2[2 * v + 1] = __floats2half2_rn(tanhf(b.z), tanhf(b.w));
}

__global__ void pack_prev(const float* __restrict__ target,
                          __half* __restrict__ prev)
{
    int idx = blockIdx.x * blockDim.x + threadIdx.x;
    if (idx >= S_DIM * NROW * DPH) return;
    int d = idx % DPH;
    int r = (idx / DPH) % NROW;
    int s = idx / (DPH * NROW);
    int e = r >> 7, b = r & 127;
    int t = e * S_DIM + s;
    float val = 0.f;
    if (d < D_DIM && t != 0)
        val = target[((size_t)b * OUT_T + (t - 1)) * D_DIM + d];
    prev[idx] = __float2half(val);
}

__global__ void repack_w1(const float* __restrict__ w,
                          __half* __restrict__ w1c, __half* __restrict__ w1p)
{
    int idx = blockIdx.x * blockDim.x + threadIdx.x;
    const int T1 = G3 * C_DIM;
    const int T2 = G3 * DPH;
    if (idx < T1) {
        int n = idx / C_DIM, k = idx % C_DIM;
        w1c[idx] = __float2half(w[(size_t)n * (C_DIM + D_DIM) + k]);
    } else if (idx < T1 + T2) {
        int j = idx - T1;
        int n = j / DPH, k = j % DPH;
        w1p[j] = __float2half(
            (k < D_DIM) ? w[(size_t)n * (C_DIM + D_DIM) + C_DIM + k] : 0.f);
    }
}

__global__ void half_copy(const float* __restrict__ src,
                          __half* __restrict__ dst, int n)
{
    int idx = blockIdx.x * blockDim.x + threadIdx.x;
    if (idx < n) dst[idx] = __float2half(src[idx]);
}

__global__ void scatter_out(const float* __restrict__ y,
                            float* __restrict__ out)
{
    int idx = blockIdx.x * blockDim.x + threadIdx.x;
    if (idx >= TROW * D_DIM) return;
    int d = idx % D_DIM;
    int m = idx / D_DIM;
    int s = m >> 11;
    int r = m & 2047;
    int e = r >> 7, b = r & 127;
    out[((size_t)b * OUT_T + e * S_DIM + s) * D_DIM + d] =
        y[(size_t)m * DPAD + d];
}

// ---------------- launch helpers ---------------------------------------------
static inline GP mk(const __half* A, int lda, const __half* B, int ldb,
                    const float* bias, void* C, int ldc, int K, int N)
{
    GP p;
    p.A = A; p.B = B; p.bias = bias; p.C = C;
    p.lda = lda; p.ldb = ldb; p.ldc = ldc; p.K = K; p.N = N;
    return p;
}
template <int OUT>
static inline void launch_gemm(GP p0, GP p1, GP p2, int M, int Nmax, int nz)
{
    cudaFuncSetAttribute(gemm4<OUT>,
                         cudaFuncAttributeMaxDynamicSharedMemorySize,
                         GSMEM_BYTES);
    dim3 grid((Nmax + 127) / 128, M / 128, nz);
    gemm4<OUT><<<grid, 128, GSMEM_BYTES>>>(p0, p1, p2);
}

extern "C" void kernel_launch(void* const* d_in, const int* in_sizes, int n_in,
                              void* d_out, int out_size)
{
    const float* c      = (const float*)d_in[0];
    const float* target = (const float*)d_in[1];
    int base = (n_in >= 16) ? 4 : 2;
    const float* fc_init_w = (const float*)d_in[base + 0];
    const float* fc_init_b = (const float*)d_in[base + 1];
    const float* g1_wih    = (const float*)d_in[base + 2];
    const float* g1_whh    = (const float*)d_in[base + 3];
    const float* g1_bih    = (const float*)d_in[base + 4];
    const float* g1_bhh    = (const float*)d_in[base + 5];
    const float* g2_wih    = (const float*)d_in[base + 6];
    const float* g2_whh    = (const float*)d_in[base + 7];
    const float* g2_bih    = (const float*)d_in[base + 8];
    const float* g2_bhh    = (const float*)d_in[base + 9];
    const float* fco_w     = (const float*)d_in[base + 10];
    const float* fco_b     = (const float*)d_in[base + 11];
    float* out = (float*)d_out;

    __half *H1h, *H2h, *HAh, *PVh, *CRh, *FIWh, *W1Ch, *W1Ph, *W1Hh, *W2Ih,
        *W2Hh, *FOh, *TAh, *TBh, *PPsh, *CPh, *T0h;
    float* Y;
    cudaGetSymbolAddress((void**)&H1h, g_H1h);
    cudaGetSymbolAddress((void**)&H2h, g_H2h);
    cudaGetSymbolAddress((void**)&HAh, g_HAh);
    cudaGetSymbolAddress((void**)&PVh, g_PVh);
    cudaGetSymbolAddress((void**)&CRh, g_CRh);
    cudaGetSymbolAddress((void**)&FIWh, g_FIWh);
    cudaGetSymbolAddress((void**)&W1Ch, g_W1Ch);
    cudaGetSymbolAddress((void**)&W1Ph, g_W1Ph);
    cudaGetSymbolAddress((void**)&W1Hh, g_W1Hh);
    cudaGetSymbolAddress((void**)&W2Ih, g_W2Ih);
    cudaGetSymbolAddress((void**)&W2Hh, g_W2Hh);
    cudaGetSymbolAddress((void**)&FOh, g_FOh);
    cudaGetSymbolAddress((void**)&TAh, g_TAh);
    cudaGetSymbolAddress((void**)&TBh, g_TBh);
    cudaGetSymbolAddress((void**)&PPsh, g_PPsh);
    cudaGetSymbolAddress((void**)&CPh, g_CPh);
    cudaGetSymbolAddress((void**)&T0h, g_T0h);
    cudaGetSymbolAddress((void**)&Y,  g_Y);

    // ---- precompute (ordered so launch #6 = cpart GEMM for ncu -s 5) ----
    repack_w1<<<(G3 * (C_DIM + DPH) + 255) / 256, 256>>>(g1_wih, W1Ch, W1Ph); //1
    pack_prev<<<(S_DIM * NROW * DPH + 255) / 256, 256>>>(target, PVh);        //2
    half_copy<<<(NROW * C_DIM + 255) / 256, 256>>>(c, CRh, NROW * C_DIM);     //3
    half_copy<<<(2 * H_DIM * C_DIM + 255) / 256, 256>>>(fc_init_w, FIWh,
                                                        2 * H_DIM * C_DIM);   //4
    half_copy<<<(G3 * H_DIM + 255) / 256, 256>>>(g1_whh, W1Hh, G3 * H_DIM);   //5
    // #6 — cpart = c @ W1C^T + g1_bih [2048x3072]: the profiled launch
    {
        GP p = mk(CRh, C_DIM, W1Ch, C_DIM, g1_bih, CPh, G3, C_DIM, G3);
        launch_gemm<0>(p, p, p, NROW, G3, 1);
    }
    half_copy<<<(G3 * H_DIM + 255) / 256, 256>>>(g2_wih, W2Ih, G3 * H_DIM);
    half_copy<<<(G3 * H_DIM + 255) / 256, 256>>>(g2_whh, W2Hh, G3 * H_DIM);
    half_copy<<<(D_DIM * H_DIM + 255) / 256, 256>>>(fco_w, FOh, D_DIM * H_DIM);
    // t0 = c @ fiw^T + b  [2048x2048]
    {
        GP p = mk(CRh, C_DIM, FIWh, C_DIM, fc_init_b, T0h, 2 * H_DIM,
                  C_DIM, 2 * H_DIM);
        launch_gemm<0>(p, p, p, NROW, 2 * H_DIM, 1);
    }
    init_tanh<<<(NROW * H_DIM / 4) / 256, 256>>>(
        (const __half2*)T0h, (__half2*)H1h, (__half2*)H2h);

    // ---- recurrent loop (single stream, R9 structure) ----
    for (int s = 0; s < S_DIM; s++) {
        GP p0 = mk(H1h, H_DIM, W1Hh, H_DIM, g1_bhh, TAh, G3, H_DIM, G3);
        GP p1 = mk(H2h, H_DIM, W2Hh, H_DIM, g2_bhh, TBh, G3, H_DIM, G3);
        GP p2 = mk(PVh + (size_t)s * NROW * DPH, DPH, W1Ph, DPH, nullptr,
                   PPsh, G3, DPH, G3);
        launch_gemm<0>(p0, p1, p2, NROW, G3, 3);
        gate_kernel<true, false><<<(NROW * H_DIM / 4) / 256, 256>>>(
            (const __half2*)CPh, (const __half2*)PPsh,
            (const __half2*)TAh, (__half2*)H1h, nullptr);
        GP pg = mk(H1h, H_DIM, W2Ih, H_DIM, g2_bih, TAh, G3, H_DIM, G3);
        launch_gemm<0>(pg, pg, pg, NROW, G3, 1);
        gate_kernel<false, true><<<(NROW * H_DIM / 4) / 256, 256>>>(
            (const __half2*)TAh, nullptr, (const __half2*)TBh,
            (__half2*)H2h, (__half2*)(HAh + (size_t)s * NROW * H_DIM));
    }

    // ---- output projection (fp32 Y, DPAD rows) + separate scatter ----------
    {
        GP p = mk(HAh, H_DIM, FOh, H_DIM, fco_b, Y, DPAD, H_DIM, D_DIM);
        launch_gemm<1>(p, p, p, TROW, D_DIM, 1);
    }
    scatter_out<<<(TROW * D_DIM + 255) / 256, 256>>>(Y, out);
}

// round 12
// speedup vs baseline: 1.2414x; 1.2414x over previous
#include <cuda_runtime.h>
#include <cuda_fp16.h>
#include <cstdint>
#include <cstddef>

#define E_DIM 16
#define B_DIM 128
#define C_DIM 512
#define H_DIM 1024
#define D_DIM 130
#define DPAD  132            // fp32 Y row pad (528B, 16B-aligned)
#define DPH   136            // half prev row pad (16B-aligned rows)
#define S_DIM 16
#define NROW  2048
#define G3    3072
#define TROW  32768
#define OUT_T 256

// ---------------- scratch (static device globals) ----------------------------
__device__ __align__(16) __half g_H1h[NROW * H_DIM];
__device__ __align__(16) __half g_H2h[NROW * H_DIM];
__device__ __align__(16) __half g_HAh[(size_t)S_DIM * NROW * H_DIM];
__device__ __align__(16) __half g_PVh[(size_t)S_DIM * NROW * DPH];
__device__ __align__(16) __half g_CRh[NROW * C_DIM];
__device__ __align__(16) __half g_FIWh[2 * H_DIM * C_DIM];
__device__ __align__(16) __half g_W1Ch[G3 * C_DIM];
__device__ __align__(16) __half g_W1Ph[G3 * DPH];
__device__ __align__(16) __half g_W1Hh[G3 * H_DIM];
__device__ __align__(16) __half g_W2Ih[G3 * H_DIM];
__device__ __align__(16) __half g_W2Hh[G3 * H_DIM];
__device__ __align__(16) __half g_FOh[D_DIM * H_DIM];
// half GEMM outputs
__device__ __align__(16) __half g_TAh[NROW * G3];
__device__ __align__(16) __half g_TBh[NROW * G3];
__device__ __align__(16) __half g_PPsh[NROW * G3];        // prev-part, this step
__device__ __align__(16) __half g_CPh[NROW * G3];
__device__ __align__(16) __half g_T0h[NROW * 2 * H_DIM];
// fp32 final projection buffer
__device__ __align__(16) float g_Y[(size_t)TROW * DPAD];

// ---------------- helpers ----------------------------------------------------
__device__ __forceinline__ uint32_t smem_u32(const void* p) {
    uint32_t a;
    asm("{ .reg .u64 t; cvta.to.shared.u64 t, %1; cvt.u32.u64 %0, t; }"
        : "=r"(a) : "l"(p));
    return a;
}
__device__ __forceinline__ void mma_f16(float d[4], const uint32_t a[4],
                                        const uint32_t b[2]) {
    asm volatile(
        "mma.sync.aligned.m16n8k16.row.col.f32.f16.f16.f32 "
        "{%0,%1,%2,%3}, {%4,%5,%6,%7}, {%8,%9}, {%0,%1,%2,%3};\n"
        : "+f"(d[0]), "+f"(d[1]), "+f"(d[2]), "+f"(d[3])
        : "r"(a[0]), "r"(a[1]), "r"(a[2]), "r"(a[3]), "r"(b[0]), "r"(b[1]));
}

// ---------------- z-batched TN GEMM (half in; OUT=0 half, OUT=1 fp32) --------
struct GP {
    const __half *A, *B;
    const float* bias;
    void* C;                 // OUT 0: __half*, OUT 1: float*
    int lda, ldb, ldc, K, N;
};

#define RS   40                      // smem row stride in halves (80 B)
#define STG_B 20480                  // bytes per stage (A 10240 + B 10240)
#define ER   136                     // epilogue fp32 row stride
#define GSMEM_BYTES (4 * STG_B)      // 81920 (epilogue 128*136*4=69632 fits)

// C[M,N] = A[M,K] * B[N,K]^T (+bias). M mult of 128. Tile 128x128x32(half),
// 4 warps (64x64), 4-stage cp.async, smem-transpose coalesced epilogue.
template <int OUT>
__global__ void __launch_bounds__(128, 2) gemm4(GP p0, GP p1, GP p2)
{
    extern __shared__ __half smh[];
    float* smf = (float*)smh;
    const GP p = (blockIdx.z == 0) ? p0 : ((blockIdx.z == 1) ? p1 : p2);
    const uint32_t smb = smem_u32(smh);
    const int tid  = threadIdx.x, lane = tid & 31, warp = tid >> 5;
    const int g    = lane >> 2, tg = lane & 3;
    const int wm   = (warp & 1) * 64, wn = (warp >> 1) * 64;
    const int bm0  = blockIdx.y * 128, bn0 = blockIdx.x * 128;
    const int KT   = (p.K + 31) / 32;
    const int lrow = tid >> 2, ci = tid & 3;

    float acc[4][8][4];
#pragma unroll
    for (int mi = 0; mi < 4; mi++)
#pragma unroll
        for (int ni = 0; ni < 8; ni++)
#pragma unroll
            for (int f = 0; f < 4; f++) acc[mi][ni][f] = 0.f;

#define LOADS(kt, st) do {                                                    \
    uint32_t ab = smb + (uint32_t)(st) * STG_B;                               \
    uint32_t bb = ab + STG_B / 2;                                             \
    int kc = (kt) * 32 + ci * 8;                                              \
    int sza = (kc < p.K) ? 16 : 0;                                            \
    _Pragma("unroll") for (int t = 0; t < 4; t++) {                           \
        int row = t * 32 + lrow;                                              \
        const __half* sa = sza ? (p.A + (size_t)(bm0 + row) * p.lda + kc)     \
                               : p.A;                                         \
        uint32_t da = ab + (uint32_t)(row * 80 + ci * 16);                    \
        asm volatile("cp.async.cg.shared.global [%0], [%1], 16, %2;"          \
                     :: "r"(da), "l"(sa), "r"(sza));                          \
        int gr = bn0 + row;                                                   \
        int szb = (sza && gr < p.N) ? 16 : 0;                                 \
        const __half* sb = szb ? (p.B + (size_t)gr * p.ldb + kc) : p.B;       \
        uint32_t db = bb + (uint32_t)(row * 80 + ci * 16);                    \
        asm volatile("cp.async.cg.shared.global [%0], [%1], 16, %2;"          \
                     :: "r"(db), "l"(sb), "r"(szb));                          \
    }                                                                         \
} while (0)

#define COMP(st) do {                                                         \
    const __half* As = smh + (size_t)(st) * (STG_B / 2);                      \
    const __half* Bs = As + STG_B / 4;                                        \
    _Pragma("unroll") for (int ks = 0; ks < 2; ks++) {                        \
        const int k0 = ks * 16 + tg * 2;                                      \
        uint32_t af[4][4], bf[8][2];                                          \
        _Pragma("unroll") for (int mi = 0; mi < 4; mi++) {                    \
            int r = wm + mi * 16 + g;                                         \
            af[mi][0] = *(const uint32_t*)&As[r * RS + k0];                   \
            af[mi][1] = *(const uint32_t*)&As[(r + 8) * RS + k0];             \
            af[mi][2] = *(const uint32_t*)&As[r * RS + k0 + 8];               \
            af[mi][3] = *(const uint32_t*)&As[(r + 8) * RS + k0 + 8];         \
        }                                                                     \
        _Pragma("unroll") for (int ni = 0; ni < 8; ni++) {                    \
            int n = wn + ni * 8 + g;                                          \
            bf[ni][0] = *(const uint32_t*)&Bs[n * RS + k0];                   \
            bf[ni][1] = *(const uint32_t*)&Bs[n * RS + k0 + 8];               \
        }                                                                     \
        _Pragma("unroll") for (int mi = 0; mi < 4; mi++)                      \
            _Pragma("unroll") for (int ni = 0; ni < 8; ni++)                  \
                mma_f16(acc[mi][ni], af[mi], bf[ni]);                         \
    }                                                                         \
} while (0)

#pragma unroll
    for (int s = 0; s < 3; s++) {
        if (s < KT) LOADS(s, s);
        asm volatile("cp.async.commit_group;" ::: "memory");
    }
    for (int kt = 0; kt < KT; kt++) {
        asm volatile("cp.async.wait_group 2;" ::: "memory");
        __syncthreads();
        COMP(kt & 3);
        int nk = kt + 3;
        if (nk < KT) LOADS(nk, nk & 3);
        asm volatile("cp.async.commit_group;" ::: "memory");
    }
    asm volatile("cp.async.wait_group 0;" ::: "memory");
#undef LOADS
#undef COMP

    // ---- epilogue: fp32 acc -> smem transpose -> coalesced stores (+bias) ---
    __syncthreads();
#pragma unroll
    for (int mi = 0; mi < 4; mi++)
#pragma unroll
        for (int ni = 0; ni < 8; ni++) {
            int r = wm + mi * 16 + g, cc = wn + ni * 8 + 2 * tg;
            *(float2*)&smf[r * ER + cc] =
                make_float2(acc[mi][ni][0], acc[mi][ni][1]);
            *(float2*)&smf[(r + 8) * ER + cc] =
                make_float2(acc[mi][ni][2], acc[mi][ni][3]);
        }
    __syncthreads();

    const int col = (tid & 31) * 4;
    const int rb  = tid >> 5;
    const int gn  = bn0 + col;
    float4 bv = make_float4(0.f, 0.f, 0.f, 0.f);
    if (p.bias) {
        if (gn < p.N)     bv.x = p.bias[gn];
        if (gn + 1 < p.N) bv.y = p.bias[gn + 1];
        if (gn + 2 < p.N) bv.z = p.bias[gn + 2];
        if (gn + 3 < p.N) bv.w = p.bias[gn + 3];
    }
#pragma unroll
    for (int j = 0; j < 32; j++) {
        int r = j * 4 + rb;
        float4 v = *(float4*)&smf[r * ER + col];
        v.x += bv.x; v.y += bv.y; v.z += bv.z; v.w += bv.w;
        if (OUT == 0) {
            __half* cp = (__half*)p.C + (size_t)(bm0 + r) * p.ldc + gn;
            if (gn + 3 < p.N) {
                __half2 o0 = __floats2half2_rn(v.x, v.y);
                __half2 o1 = __floats2half2_rn(v.z, v.w);
                *(uint2*)cp = make_uint2(*(uint32_t*)&o0, *(uint32_t*)&o1);
            } else {
                if (gn < p.N)     cp[0] = __float2half(v.x);
                if (gn + 1 < p.N) cp[1] = __float2half(v.y);
                if (gn + 2 < p.N) cp[2] = __float2half(v.z);
                if (gn + 3 < p.N) cp[3] = __float2half(v.w);
            }
        } else {
            float* cp = (float*)p.C + (size_t)(bm0 + r) * p.ldc + gn;
            if (gn + 3 < p.N) {
                *(float4*)cp = v;
            } else {
                if (gn < p.N)     cp[0] = v.x;
                if (gn + 1 < p.N) cp[1] = v.y;
                if (gn + 2 < p.N) cp[2] = v.z;
            }
        }
    }
}

// ---------------- elementwise kernels ----------------------------------------
__device__ __forceinline__ float sigf(float x) {
    return 1.f / (1.f + __expf(-x));
}
__device__ __forceinline__ float4 h4(const __half2* p, int i) {
    __half2 a = p[i], b = p[i + 1];
    return make_float4(__low2float(a), __high2float(a),
                       __low2float(b), __high2float(b));
}

// gi = gi1 (+gi2) (half); gh half; h half. 4 units/thread.
template <bool HAS_GI2, bool HAS_COPY>
__global__ void gate_kernel(const __half2* __restrict__ gi1,
                            const __half2* __restrict__ gi2,
                            const __half2* __restrict__ gh,
                            __half2* __restrict__ h,
                            __half2* __restrict__ hcopy)
{
    int v = blockIdx.x * blockDim.x + threadIdx.x;   // NROW*H/4
    int m = v >> 8, q = v & 255;
    int base = m * 1536 + 2 * q;                     // half2 units, G3/2=1536
    float4 ir = h4(gi1, base), iz = h4(gi1, base + 512),
           in = h4(gi1, base + 1024);
    if (HAS_GI2) {
        float4 a = h4(gi2, base), b = h4(gi2, base + 512),
               c = h4(gi2, base + 1024);
        ir.x += a.x; ir.y += a.y; ir.z += a.z; ir.w += a.w;
        iz.x += b.x; iz.y += b.y; iz.z += b.z; iz.w += b.w;
        in.x += c.x; in.y += c.y; in.z += c.z; in.w += c.w;
    }
    float4 hr = h4(gh, base), hz = h4(gh, base + 512),
           hn = h4(gh, base + 1024);
    float4 hv = h4(h, 2 * v);
    float4 o;
#define GATE1(cmp)                                                            \
    { float r = sigf(ir.cmp + hr.cmp), z = sigf(iz.cmp + hz.cmp);             \
      float n = tanhf(in.cmp + r * hn.cmp);                                   \
      o.cmp = (1.f - z) * n + z * hv.cmp; }
    GATE1(x) GATE1(y) GATE1(z) GATE1(w)
#undef GATE1
    __half2 o0 = __floats2half2_rn(o.x, o.y);
    __half2 o1 = __floats2half2_rn(o.z, o.w);
    h[2 * v] = o0;
    h[2 * v + 1] = o1;
    if (HAS_COPY) {
        hcopy[2 * v] = o0;
        hcopy[2 * v + 1] = o1;
    }
}

__global__ void init_tanh(const __half2* __restrict__ t0,
                          __half2* __restrict__ h1, __half2* __restrict__ h2)
{
    int v = blockIdx.x * blockDim.x + threadIdx.x;
    int m = v >> 8, q = v & 255;
    float4 a = h4(t0, m * 1024 + 2 * q);
    float4 b = h4(t0, m * 1024 + 512 + 2 * q);
    h1[2 * v]     = __floats2half2_rn(tanhf(a.x), tanhf(a.y));
    h1[2 * v + 1] = __floats2half2_rn(tanhf(a.z), tanhf(a.w));
    h2[2 * v]     = __floats2half2_rn(tanhf(b.x), tanhf(b.y));
    h2[2 * v + 1] = __floats2half2_rn(tanhf(b.z), tanhf(b.w));
}

__global__ void pack_prev(const float* __restrict__ target,
                          __half* __restrict__ prev)
{
    int idx = blockIdx.x * blockDim.x + threadIdx.x;
    if (idx >= S_DIM * NROW * DPH) return;
    int d = idx % DPH;
    int r = (idx / DPH) % NROW;
    int s = idx / (DPH * NROW);
    int e = r >> 7, b = r & 127;
    int t = e * S_DIM + s;
    float val = 0.f;
    if (d < D_DIM && t != 0)
        val = target[((size_t)b * OUT_T + (t - 1)) * D_DIM + d];
    prev[idx] = __float2half(val);
}

__global__ void repack_w1(const float* __restrict__ w,
                          __half* __restrict__ w1c, __half* __restrict__ w1p)
{
    int idx = blockIdx.x * blockDim.x + threadIdx.x;
    const int T1 = G3 * C_DIM;
    const int T2 = G3 * DPH;
    if (idx < T1) {
        int n = idx / C_DIM, k = idx % C_DIM;
        w1c[idx] = __float2half(w[(size_t)n * (C_DIM + D_DIM) + k]);
    } else if (idx < T1 + T2) {
        int j = idx - T1;
        int n = j / DPH, k = j % DPH;
        w1p[j] = __float2half(
            (k < D_DIM) ? w[(size_t)n * (C_DIM + D_DIM) + C_DIM + k] : 0.f);
    }
}

// one kernel converting all fp32->half operand arrays (replaces 6 half_copy)
struct CvtJob { const float* src; __half* dst; int n; };
__global__ void convert_all(CvtJob j0, CvtJob j1, CvtJob j2, CvtJob j3,
                            CvtJob j4, CvtJob j5)
{
    int idx = blockIdx.x * blockDim.x + threadIdx.x;
    CvtJob j;
    // jobs laid out back-to-back in one index space
    if (idx < j0.n)            { j = j0; }
    else if ((idx -= j0.n) < j1.n) { j = j1; }
    else if ((idx -= j1.n) < j2.n) { j = j2; }
    else if ((idx -= j2.n) < j3.n) { j = j3; }
    else if ((idx -= j3.n) < j4.n) { j = j4; }
    else if ((idx -= j4.n) < j5.n) { j = j5; }
    else return;
    j.dst[idx] = __float2half(j.src[idx]);
}

__global__ void scatter_out(const float* __restrict__ y,
                            float* __restrict__ out)
{
    int idx = blockIdx.x * blockDim.x + threadIdx.x;
    if (idx >= TROW * D_DIM) return;
    int d = idx % D_DIM;
    int m = idx / D_DIM;
    int s = m >> 11;
    int r = m & 2047;
    int e = r >> 7, b = r & 127;
    out[((size_t)b * OUT_T + e * S_DIM + s) * D_DIM + d] =
        y[(size_t)m * DPAD + d];
}

// ---------------- launch helpers ---------------------------------------------
static inline GP mk(const __half* A, int lda, const __half* B, int ldb,
                    const float* bias, void* C, int ldc, int K, int N)
{
    GP p;
    p.A = A; p.B = B; p.bias = bias; p.C = C;
    p.lda = lda; p.ldb = ldb; p.ldc = ldc; p.K = K; p.N = N;
    return p;
}
template <int OUT>
static inline void launch_gemm(GP p0, GP p1, GP p2, int M, int Nmax, int nz)
{
    cudaFuncSetAttribute(gemm4<OUT>,
                         cudaFuncAttributeMaxDynamicSharedMemorySize,
                         GSMEM_BYTES);
    dim3 grid((Nmax + 127) / 128, M / 128, nz);
    gemm4<OUT><<<grid, 128, GSMEM_BYTES>>>(p0, p1, p2);
}

extern "C" void kernel_launch(void* const* d_in, const int* in_sizes, int n_in,
                              void* d_out, int out_size)
{
    const float* c      = (const float*)d_in[0];
    const float* target = (const float*)d_in[1];
    int base = (n_in >= 16) ? 4 : 2;
    const float* fc_init_w = (const float*)d_in[base + 0];
    const float* fc_init_b = (const float*)d_in[base + 1];
    const float* g1_wih    = (const float*)d_in[base + 2];
    const float* g1_whh    = (const float*)d_in[base + 3];
    const float* g1_bih    = (const float*)d_in[base + 4];
    const float* g1_bhh    = (const float*)d_in[base + 5];
    const float* g2_wih    = (const float*)d_in[base + 6];
    const float* g2_whh    = (const float*)d_in[base + 7];
    const float* g2_bih    = (const float*)d_in[base + 8];
    const float* g2_bhh    = (const float*)d_in[base + 9];
    const float* fco_w     = (const float*)d_in[base + 10];
    const float* fco_b     = (const float*)d_in[base + 11];
    float* out = (float*)d_out;

    __half *H1h, *H2h, *HAh, *PVh, *CRh, *FIWh, *W1Ch, *W1Ph, *W1Hh, *W2Ih,
        *W2Hh, *FOh, *TAh, *TBh, *PPsh, *CPh, *T0h;
    float* Y;
    cudaGetSymbolAddress((void**)&H1h, g_H1h);
    cudaGetSymbolAddress((void**)&H2h, g_H2h);
    cudaGetSymbolAddress((void**)&HAh, g_HAh);
    cudaGetSymbolAddress((void**)&PVh, g_PVh);
    cudaGetSymbolAddress((void**)&CRh, g_CRh);
    cudaGetSymbolAddress((void**)&FIWh, g_FIWh);
    cudaGetSymbolAddress((void**)&W1Ch, g_W1Ch);
    cudaGetSymbolAddress((void**)&W1Ph, g_W1Ph);
    cudaGetSymbolAddress((void**)&W1Hh, g_W1Hh);
    cudaGetSymbolAddress((void**)&W2Ih, g_W2Ih);
    cudaGetSymbolAddress((void**)&W2Hh, g_W2Hh);
    cudaGetSymbolAddress((void**)&FOh, g_FOh);
    cudaGetSymbolAddress((void**)&TAh, g_TAh);
    cudaGetSymbolAddress((void**)&TBh, g_TBh);
    cudaGetSymbolAddress((void**)&PPsh, g_PPsh);
    cudaGetSymbolAddress((void**)&CPh, g_CPh);
    cudaGetSymbolAddress((void**)&T0h, g_T0h);
    cudaGetSymbolAddress((void**)&Y,  g_Y);

    // ---- precompute ----
    // launches: 1 repack_w1, 2 pack_prev, 3 convert_all, 4 cpart GEMM
    // (harness prepends ~2 internal launches; ncu -s 5 should land on #4)
    repack_w1<<<(G3 * (C_DIM + DPH) + 255) / 256, 256>>>(g1_wih, W1Ch, W1Ph);
    pack_prev<<<(S_DIM * NROW * DPH + 255) / 256, 256>>>(target, PVh);
    {
        CvtJob j0 = { c,         CRh,  NROW * C_DIM };
        CvtJob j1 = { fc_init_w, FIWh, 2 * H_DIM * C_DIM };
        CvtJob j2 = { g1_whh,    W1Hh, G3 * H_DIM };
        CvtJob j3 = { g2_wih,    W2Ih, G3 * H_DIM };
        CvtJob j4 = { g2_whh,    W2Hh, G3 * H_DIM };
        CvtJob j5 = { fco_w,     FOh,  D_DIM * H_DIM };
        int total = j0.n + j1.n + j2.n + j3.n + j4.n + j5.n;
        convert_all<<<(total + 255) / 256, 256>>>(j0, j1, j2, j3, j4, j5);
    }
    // cpart = c @ W1C^T + g1_bih  [2048x3072]   <-- profiled launch
    {
        GP p = mk(CRh, C_DIM, W1Ch, C_DIM, g1_bih, CPh, G3, C_DIM, G3);
        launch_gemm<0>(p, p, p, NROW, G3, 1);
    }
    // t0 = c @ fiw^T + b  [2048x2048]
    {
        GP p = mk(CRh, C_DIM, FIWh, C_DIM, fc_init_b, T0h, 2 * H_DIM,
                  C_DIM, 2 * H_DIM);
        launch_gemm<0>(p, p, p, NROW, 2 * H_DIM, 1);
    }
    init_tanh<<<(NROW * H_DIM / 4) / 256, 256>>>(
        (const __half2*)T0h, (__half2*)H1h, (__half2*)H2h);

    // ---- recurrent loop (R9 structure, unchanged) ----
    for (int s = 0; s < S_DIM; s++) {
        GP p0 = mk(H1h, H_DIM, W1Hh, H_DIM, g1_bhh, TAh, G3, H_DIM, G3);
        GP p1 = mk(H2h, H_DIM, W2Hh, H_DIM, g2_bhh, TBh, G3, H_DIM, G3);
        GP p2 = mk(PVh + (size_t)s * NROW * DPH, DPH, W1Ph, DPH, nullptr,
                   PPsh, G3, DPH, G3);
        launch_gemm<0>(p0, p1, p2, NROW, G3, 3);
        gate_kernel<true, false><<<(NROW * H_DIM / 4) / 256, 256>>>(
            (const __half2*)CPh, (const __half2*)PPsh,
            (const __half2*)TAh, (__half2*)H1h, nullptr);
        GP pg = mk(H1h, H_DIM, W2Ih, H_DIM, g2_bih, TAh, G3, H_DIM, G3);
        launch_gemm<0>(pg, pg, pg, NROW, G3, 1);
        gate_kernel<false, true><<<(NROW * H_DIM / 4) / 256, 256>>>(
            (const __half2*)TAh, nullptr, (const __half2*)TBh,
            (__half2*)H2h, (__half2*)(HAh + (size_t)s * NROW * H_DIM));
    }

    // ---- output projection (fp32 Y, DPAD rows) + separate scatter ----------
    {
        GP p = mk(HAh, H_DIM, FOh, H_DIM, fco_b, Y, DPAD, H_DIM, D_DIM);
        launch_gemm<1>(p, p, p, TROW, D_DIM, 1);
    }
    scatter_out<<<(TROW * D_DIM + 255) / 256, 256>>>(Y, out);
}